// round 7
// baseline (speedup 1.0000x reference)
#include <cuda_runtime.h>
#include <cuda_fp16.h>
#include <stdint.h>

#define MAXN 50000
#define MAXE 800000
#define XD 32
#define HD 96
#define OD 64
#define NB256 ((MAXN + 255) / 256)
#define PQBLK 391     // ceil(50000/128)
#define HBLK  800

// ---- device scratch ----
__device__ float2  g_WAB[HD * XD];          // interleaved {A[j][r], B[j][r]}
__device__ float   g_c[HD];
__device__ float   g_p[MAXN * HD];
__device__ __half2 g_qh[MAXN * (HD / 2)];
__device__ int     g_deg[MAXN];
__device__ int     g_off[MAXN + 1];
__device__ int     g_rank[MAXE];
__device__ int     g_srcs[MAXE];
__device__ int     g_bsum[NB256];
__device__ int     g_is64;
__device__ int     g_scount = 0;
__device__ volatile int g_sgen = 0;

// ---- f32x2 packed helpers (sm_103a) ----
__device__ __forceinline__ unsigned long long pack2(float lo, float hi) {
    unsigned long long d;
    asm("mov.b64 %0, {%1, %2};" : "=l"(d) : "f"(lo), "f"(hi));
    return d;
}
__device__ __forceinline__ void unpack2(float& lo, float& hi, unsigned long long v) {
    asm("mov.b64 {%0, %1}, %2;" : "=f"(lo), "=f"(hi) : "l"(v));
}
__device__ __forceinline__ unsigned long long fma2(unsigned long long a,
                                                   unsigned long long b,
                                                   unsigned long long c) {
    unsigned long long d;
    asm("fma.rn.f32x2 %0, %1, %2, %3;" : "=l"(d) : "l"(a), "l"(b), "l"(c));
    return d;
}

__device__ __forceinline__ int load_idx(const void* ei, int i) {
    if (g_is64) return (int)((const long long*)ei)[i];
    return ((const int*)ei)[i];
}

__device__ __forceinline__ int warp_reduce(int v) {
#pragma unroll
    for (int o = 16; o > 0; o >>= 1) v += __shfl_down_sync(0xffffffffu, v, o);
    return v;
}

// ---- init: zero deg; block 0 detects dtype + builds WAB/c ----
__global__ void init_kernel(const float* __restrict__ W1,
                            const float* __restrict__ b1,
                            const float* __restrict__ scalars,
                            const int* __restrict__ ei32, int n) {
    int i = blockIdx.x * blockDim.x + threadIdx.x;
    if (i < n) g_deg[i] = 0;
    if (blockIdx.x == 0) {
        __shared__ int s_any;
        if (threadIdx.x == 0) s_any = 0;
        __syncthreads();
        for (int k = threadIdx.x; k < 1024; k += blockDim.x)
            if (ei32[2 * k + 1] != 0) s_any = 1;
        __syncthreads();
        if (threadIdx.x == 0) g_is64 = (s_any == 0) ? 1 : 0;
        int j = threadIdx.x;
        if (j < HD) {
            float c = b1[j];
#pragma unroll
            for (int s = 0; s < 16; s++) c += scalars[s] * W1[(32 + s) * HD + j];
            g_c[j] = c;
#pragma unroll
            for (int r = 0; r < XD; r++) {
                float wB = W1[(48 + r) * HD + j];
                g_WAB[j * XD + r] = make_float2(W1[r * HD + j] - wB, wB);
            }
        }
    }
}

// ---- fused: pq (f32x2, thread-per-node) + hist ----
__global__ void __launch_bounds__(128)
pqhist_kernel(const float* __restrict__ x, const void* __restrict__ ei,
              int n, int e) {
    __shared__ float2 sWAB[HD * XD];      // 24KB
    __shared__ float  sc[HD];
    __shared__ float  xs[128][XD + 1];
    const int tid = threadIdx.x;

    if (blockIdx.x < PQBLK) {
        for (int i = tid; i < HD * XD; i += 128) sWAB[i] = g_WAB[i];
        if (tid < HD) sc[tid] = g_c[tid];
        const int base = blockIdx.x * 128;
        const int cnt = min(128, n - base);
        for (int i = tid; i < cnt * XD; i += 128)
            xs[i >> 5][i & 31] = x[(size_t)base * XD + i];
        __syncthreads();

        const int node = base + tid;
        if (tid < cnt) {
            float xr[XD];
#pragma unroll
            for (int r = 0; r < XD; r++) xr[r] = xs[tid][r];

#pragma unroll 1
            for (int jc = 0; jc < 12; jc++) {
                unsigned long long acc[8];
#pragma unroll
                for (int u = 0; u < 8; u++) acc[u] = pack2(sc[jc * 8 + u], 0.0f);
#pragma unroll
                for (int r2 = 0; r2 < 16; r2++) {
                    unsigned long long xx0 = pack2(xr[2 * r2], xr[2 * r2]);
                    unsigned long long xx1 = pack2(xr[2 * r2 + 1], xr[2 * r2 + 1]);
#pragma unroll
                    for (int u = 0; u < 8; u++) {
                        ulonglong2 wv = *(const ulonglong2*)&sWAB[(jc * 8 + u) * XD + 2 * r2];
                        acc[u] = fma2(xx0, wv.x, acc[u]);
                        acc[u] = fma2(xx1, wv.y, acc[u]);
                    }
                }
                float pa[8], qa[8];
#pragma unroll
                for (int u = 0; u < 8; u++) unpack2(pa[u], qa[u], acc[u]);
                float4* gp = (float4*)(g_p + (size_t)node * HD + jc * 8);
                gp[0] = make_float4(pa[0], pa[1], pa[2], pa[3]);
                gp[1] = make_float4(pa[4], pa[5], pa[6], pa[7]);
                __half2 h[4];
                h[0] = __floats2half2_rn(qa[0], qa[1]);
                h[1] = __floats2half2_rn(qa[2], qa[3]);
                h[2] = __floats2half2_rn(qa[4], qa[5]);
                h[3] = __floats2half2_rn(qa[6], qa[7]);
                ((uint4*)g_qh)[(size_t)node * 12 + jc] = *(uint4*)h;
            }
        }
    } else {
        const int hb = blockIdx.x - PQBLK;
        for (int i = hb * 128 + tid; i < e; i += HBLK * 128) {
            int dst = load_idx(ei, e + i);
            g_rank[i] = atomicAdd(&g_deg[dst], 1);
        }
    }
}

// ---- merged scan: block sums -> grid barrier -> offsets ----
__global__ void scan_kernel(int n, int nb) {
    __shared__ int wsum[8];
    __shared__ int wpre[8];
    __shared__ int sbase;
    const int tid = threadIdx.x;
    const int lane = tid & 31, wid = tid >> 5;
    const int b = blockIdx.x;
    const int i = b * 256 + tid;
    const int v = (i < n) ? g_deg[i] : 0;

    int s = warp_reduce(v);
    if (lane == 0) wsum[wid] = s;
    __syncthreads();
    if (tid < 8) {
        int t = wsum[tid];
#pragma unroll
        for (int o = 4; o > 0; o >>= 1) t += __shfl_down_sync(0xffu, t, o);
        if (tid == 0) g_bsum[b] = t;
    }
    // grid barrier (all nb blocks are co-resident: 256 thr, tiny smem)
    __syncthreads();
    if (tid == 0) {
        __threadfence();
        int gen = g_sgen;
        if (atomicAdd(&g_scount, 1) == nb - 1) {
            g_scount = 0;
            __threadfence();
            g_sgen = gen + 1;
        } else {
            while (g_sgen == gen) { __nanosleep(32); }
        }
        __threadfence();
    }
    __syncthreads();

    if (tid < 32) {
        int ss = 0;
        for (int k = tid; k < b; k += 32) ss += g_bsum[k];
        ss = warp_reduce(ss);
        if (tid == 0) sbase = ss;
    }
    int incl = v;
#pragma unroll
    for (int o = 1; o < 32; o <<= 1) {
        int t = __shfl_up_sync(0xffffffffu, incl, o);
        if (lane >= o) incl += t;
    }
    if (lane == 31) wpre[wid] = incl;
    __syncthreads();
    if (tid == 0) {
        int run = 0;
#pragma unroll
        for (int k = 0; k < 8; k++) { int t = wpre[k]; wpre[k] = run; run += t; }
    }
    __syncthreads();
    if (i < n) {
        int excl = sbase + wpre[wid] + incl - v;
        g_off[i] = excl;
        if (i == n - 1) g_off[n] = excl + v;
    }
}

// ---- deterministic scatter ----
__global__ void scatter_kernel(const void* __restrict__ ei, int e) {
    int i = blockIdx.x * blockDim.x + threadIdx.x;
    if (i >= e) return;
    int src = load_idx(ei, i);
    int dst = load_idx(ei, e + i);
    g_srcs[g_off[dst] + g_rank[i]] = src;
}

// ---- fused edge accumulation (uint2/lane gathers, 8-edge unroll) + out GEMM ----
__global__ void edgeout_kernel(const float* __restrict__ W2,
                               const float* __restrict__ b2,
                               float* __restrict__ out, int n) {
    __shared__ float sW2[HD * OD];
    __shared__ float sb2[OD];
    __shared__ float zbuf[8][HD];
    const int tid = threadIdx.x;
    for (int i = tid; i < HD * OD; i += 256) sW2[i] = W2[i];
    if (tid < OD) sb2[tid] = b2[tid];
    __syncthreads();

    const int w = tid >> 5, lane = tid & 31;
    const int node = blockIdx.x * 8 + w;
    if (node >= n) return;

    const int off0 = __ldg(&g_off[node]);
    const int off1 = __ldg(&g_off[node + 1]);
    // lanes 0..23 own dims 4*lane .. 4*lane+3
    float4 pp = make_float4(0.f, 0.f, 0.f, 0.f);
    if (lane < 24) pp = *(const float4*)(g_p + (size_t)node * HD + lane * 4);
    float zx = 0.f, zy = 0.f, zz = 0.f, zw = 0.f;
    const uint2 zero2 = make_uint2(0u, 0u);

    for (int base = off0; base < off1; base += 32) {
        int cnt = min(32, off1 - base);
        int sreg = (lane < cnt) ? __ldg(&g_srcs[base + lane]) : 0;
        int k = 0;
        for (; k + 7 < cnt; k += 8) {
            uint2 v[8];
#pragma unroll
            for (int u = 0; u < 8; u++) {
                int su = __shfl_sync(0xffffffffu, sreg, k + u);
                v[u] = (lane < 24)
                     ? __ldg((const uint2*)(g_qh + (size_t)su * 48) + lane)
                     : zero2;
            }
#pragma unroll
            for (int u = 0; u < 8; u++) {
                float2 f0 = __half22float2(*(__half2*)&v[u].x);
                float2 f1 = __half22float2(*(__half2*)&v[u].y);
                zx += fmaxf(pp.x + f0.x, 0.f);
                zy += fmaxf(pp.y + f0.y, 0.f);
                zz += fmaxf(pp.z + f1.x, 0.f);
                zw += fmaxf(pp.w + f1.y, 0.f);
            }
        }
        for (; k < cnt; k++) {
            int su = __shfl_sync(0xffffffffu, sreg, k);
            uint2 v0 = (lane < 24)
                     ? __ldg((const uint2*)(g_qh + (size_t)su * 48) + lane)
                     : zero2;
            float2 f0 = __half22float2(*(__half2*)&v0.x);
            float2 f1 = __half22float2(*(__half2*)&v0.y);
            zx += fmaxf(pp.x + f0.x, 0.f);
            zy += fmaxf(pp.y + f0.y, 0.f);
            zz += fmaxf(pp.z + f1.x, 0.f);
            zw += fmaxf(pp.w + f1.y, 0.f);
        }
    }
    if (lane < 24) *(float4*)&zbuf[w][lane * 4] = make_float4(zx, zy, zz, zw);
    __syncwarp();

    const int deg = off1 - off0;
    float a0 = (float)deg * sb2[lane];
    float a1 = (float)deg * sb2[lane + 32];
#pragma unroll
    for (int kk = 0; kk < HD; kk++) {
        float zv = zbuf[w][kk];
        a0 = fmaf(zv, sW2[kk * OD + lane], a0);
        a1 = fmaf(zv, sW2[kk * OD + lane + 32], a1);
    }
    out[(size_t)node * OD + lane] = a0;
    out[(size_t)node * OD + lane + 32] = a1;
}

extern "C" void kernel_launch(void* const* d_in, const int* in_sizes, int n_in,
                              void* d_out, int out_size) {
    const float* x       = (const float*)d_in[0];
    const float* scalars = (const float*)d_in[1];
    const float* W1      = (const float*)d_in[2];
    const float* b1      = (const float*)d_in[3];
    const float* W2      = (const float*)d_in[4];
    const float* b2      = (const float*)d_in[5];
    const void*  ei      = d_in[6];
    float* out = (float*)d_out;

    int n = in_sizes[0] / XD;   // 50000
    int e = in_sizes[6] / 2;    // 800000
    int nb = (n + 255) / 256;

    init_kernel<<<nb, 256>>>(W1, b1, scalars, (const int*)ei, n);
    pqhist_kernel<<<PQBLK + HBLK, 128>>>(x, ei, n, e);
    scan_kernel<<<nb, 256>>>(n, nb);
    scatter_kernel<<<(e + 255) / 256, 256>>>(ei, e);
    edgeout_kernel<<<(n + 7) / 8, 256>>>(W2, b2, out, n);
}